// round 12
// baseline (speedup 1.0000x reference)
#include <cuda_runtime.h>
#include <cuda_fp16.h>
#include <cstdint>

// ---------------- problem constants ----------------
#define IN_F   4096
#define OUT_F  16384
#define NTOK   64
#define RANK   64

#define BLOCK_M 128          // out-features per CTA
#define KBLK    64           // K elems per chunk
#define THREADS 256
#define NCHUNK_MAIN (IN_F / KBLK)             // 64
#define NCHUNK_TOT  (NCHUNK_MAIN + 1)         // 65 (lora tail chunk)

// ---------------- main-kernel SMEM layout (55 KB) ----------------
#define PH         72                          // fp16 row pitch (halfs); 144B rows
#define OFF_WH     0                           // single fp16 W buffer
#define WH_BYTES   (BLOCK_M * PH * 2)          // 18432
#define OFF_XH     WH_BYTES                    // 18432
#define XH_STAGE_B (NTOK * PH * 2)             // 9216
#define SMEM_BYTES (OFF_XH + 4 * XH_STAGE_B)   // 55296

// device scratch
__device__ __align__(256) __half g_xh[NTOK * IN_F];    // x in fp16
__device__ __align__(256) __half g_t2h[NTOK * RANK];   // 2*(x@A^T) in fp16
__device__ __align__(256) float  g_part[64 * NTOK * RANK];  // K-slice partials

// ---------------- PTX helpers ----------------
__device__ __forceinline__ uint32_t smem_u32(const void* p) {
    uint32_t a;
    asm("{ .reg .u64 t; cvta.to.shared.u64 t, %1; cvt.u32.u64 %0, t; }" : "=r"(a) : "l"(p));
    return a;
}
__device__ __forceinline__ void cp16(uint32_t dst, const void* src) {
    asm volatile("cp.async.cg.shared.global [%0], [%1], 16;" :: "r"(dst), "l"(src));
}
#define CP_COMMIT() asm volatile("cp.async.commit_group;" ::: "memory")
#define CP_WAITG2() asm volatile("cp.async.wait_group 2;" ::: "memory")

__device__ __forceinline__ void ldsm4(uint32_t* r, uint32_t addr) {
    asm volatile("ldmatrix.sync.aligned.m8n8.x4.shared.b16 {%0,%1,%2,%3}, [%4];"
                 : "=r"(r[0]), "=r"(r[1]), "=r"(r[2]), "=r"(r[3]) : "r"(addr));
}
__device__ __forceinline__ void mma_f16(float* d, const uint32_t* a,
                                        uint32_t b0, uint32_t b1) {
    asm volatile(
        "mma.sync.aligned.m16n8k16.row.col.f32.f16.f16.f32 "
        "{%0,%1,%2,%3}, {%4,%5,%6,%7}, {%8,%9}, {%0,%1,%2,%3};"
        : "+f"(d[0]), "+f"(d[1]), "+f"(d[2]), "+f"(d[3])
        : "r"(a[0]), "r"(a[1]), "r"(a[2]), "r"(a[3]), "r"(b0), "r"(b1));
}
__device__ __forceinline__ uint32_t h2u(__half2 h) {
    return *reinterpret_cast<uint32_t*>(&h);
}
__device__ __forceinline__ float dot4(float4 a, float4 b) {
    return a.x * b.x + a.y * b.y + a.z * b.z + a.w * b.w;
}

// ---------------- prep: grid 64 (one wave). x2h slice + t2 K-slice partial ----------
__global__ void __launch_bounds__(256) prep_kernel(const float* __restrict__ x,
                                                   const float* __restrict__ A,
                                                   uint2* __restrict__ xh2,
                                                   float* __restrict__ part) {
    int tid = threadIdx.x;
    int s = blockIdx.x;                       // 0..63
    // ---- x -> fp16: 65536 float4 over 64 blocks = 4/thread ----
    {
        const float4* x4 = (const float4*)x;
        int base = s * 1024;
#pragma unroll
        for (int i = 0; i < 4; ++i) {
            int idx = base + tid + i * 256;
            float4 v = x4[idx];
            uint2 o;
            o.x = h2u(__floats2half2_rn(v.x, v.y));
            o.y = h2u(__floats2half2_rn(v.z, v.w));
            xh2[idx] = o;
        }
    }
    // ---- t2 partial for K-slice s ----
    __shared__ float4 xs[64][17];
    __shared__ float4 as[64][17];
#pragma unroll
    for (int i = 0; i < 4; ++i) {
        int idx = tid + i * 256;
        int row = idx >> 4, c = idx & 15;
        xs[row][c] = ((const float4*)x)[(size_t)row * (IN_F / 4) + s * 16 + c];
        as[row][c] = ((const float4*)A)[(size_t)row * (IN_F / 4) + s * 16 + c];
    }
    __syncthreads();
    int ti = tid >> 4, tj = tid & 15;
    float acc[4][4];
#pragma unroll
    for (int r = 0; r < 4; ++r)
#pragma unroll
        for (int c = 0; c < 4; ++c) acc[r][c] = 0.f;
#pragma unroll
    for (int kc = 0; kc < 16; ++kc) {
        float4 xv[4], av[4];
#pragma unroll
        for (int r = 0; r < 4; ++r) xv[r] = xs[ti * 4 + r][kc];
#pragma unroll
        for (int c = 0; c < 4; ++c) av[c] = as[tj * 4 + c][kc];
#pragma unroll
        for (int r = 0; r < 4; ++r)
#pragma unroll
            for (int c = 0; c < 4; ++c) acc[r][c] += dot4(xv[r], av[c]);
    }
    float* dst = part + (size_t)s * (NTOK * RANK);
#pragma unroll
    for (int r = 0; r < 4; ++r)
#pragma unroll
        for (int c = 0; c < 4; ++c)
            dst[(ti * 4 + r) * RANK + tj * 4 + c] = acc[r][c];
}

// ---------------- reduce: 64 partials -> t2h = fp16(2*sum); 8-way MLP ------------
__global__ void __launch_bounds__(256) reduce_kernel(const float* __restrict__ part,
                                                     __half* __restrict__ t2) {
    int idx = blockIdx.x * 256 + threadIdx.x;     // 0..4095
    float s[8];
#pragma unroll
    for (int j = 0; j < 8; ++j) s[j] = 0.f;
#pragma unroll
    for (int b = 0; b < 64; b += 8)
#pragma unroll
        for (int j = 0; j < 8; ++j)
            s[j] += part[(size_t)(b + j) * 4096 + idx];
    float r = ((s[0] + s[1]) + (s[2] + s[3])) + ((s[4] + s[5]) + (s[6] + s[7]));
    t2[idx] = __float2half_rn(2.0f * r);
}

// ---------------- main fused GEMM ----------------
// 128 CTAs, 256 threads (8 warps: 4M x 2N), KBLK=64.
// W: LDG fp32 -> regs (double buffer, distance 2) -> cvt -> STS fp16 (no fp32 staging).
// X: 4-deep cp.async ring (wait depth 2). Two barriers/iter (R11-proven schedule).
__global__ void __launch_bounds__(THREADS, 1) lora_main_kernel(
    const __half* __restrict__ xh,     // [64,4096] fp16
    const float*  __restrict__ w,      // [16384,4096] fp32
    const float*  __restrict__ lB,     // [16384,64] fp32
    const __half* __restrict__ t2h,    // [64,64] fp16 (incl. 2x scale)
    float* __restrict__ out)           // [64,16384]
{
    extern __shared__ __align__(16) char smem_c[];
    const uint32_t sb = smem_u32(smem_c);
    const int tid  = threadIdx.x;
    const int wid  = tid >> 5;
    const int lane = tid & 31;
    const int g = lane >> 2;
    const int t = lane & 3;
    const int wm = (wid & 3) * 32;    // warp M offset
    const int wn = (wid >> 2) * 32;   // warp N offset (tokens)
    const int m_base = blockIdx.x * BLOCK_M;

    // ---- per-lane ldmatrix offsets (pitch 144B: conflict-free, banks 4r/phase) ----
    const int a_row  = (lane & 7) + ((lane >> 3) & 1) * 8;
    const uint32_t a_byte = ((lane >> 4) & 1) * 16;
    const uint32_t a_rel0 = (uint32_t)(wm + a_row) * (PH * 2) + a_byte;
    const uint32_t a_rel1 = a_rel0 + 16 * (PH * 2);
    const int b_row  = (lane & 7) + ((lane >> 4) & 1) * 8;
    const uint32_t b_byte = ((lane >> 3) & 1) * 16;
    const uint32_t b_rel0 = (uint32_t)(wn + b_row) * (PH * 2) + b_byte;
    const uint32_t b_rel1 = b_rel0 + 16 * (PH * 2);

    // ---- W register staging: thread = (row = tid>>1, half = tid&1), 32 floats ----
    const int wrow  = tid >> 1;
    const int whalf = tid & 1;
    auto ldg_w = [&](int chunk, float4* r) {
        const float4* p;
        if (chunk < NCHUNK_MAIN)
            p = (const float4*)(w + (size_t)(m_base + wrow) * IN_F
                                + chunk * KBLK + whalf * 32);
        else
            p = (const float4*)(lB + (size_t)(m_base + wrow) * RANK + whalf * 32);
#pragma unroll
        for (int i = 0; i < 8; ++i) r[i] = p[i];
    };
    __half* const wh_my = (__half*)(smem_c + OFF_WH) + wrow * PH + whalf * 32;
    auto sts_w = [&](const float4* r) {
#pragma unroll
        for (int q = 0; q < 4; ++q) {
            uint4 pk;
            pk.x = h2u(__floats2half2_rn(r[2 * q].x,     r[2 * q].y));
            pk.y = h2u(__floats2half2_rn(r[2 * q].z,     r[2 * q].w));
            pk.z = h2u(__floats2half2_rn(r[2 * q + 1].x, r[2 * q + 1].y));
            pk.w = h2u(__floats2half2_rn(r[2 * q + 1].z, r[2 * q + 1].w));
            ((uint4*)(wh_my + q * 8))[0] = pk;   // STS.128, conflict-free phases
        }
    };

    // ---- X stage loader (cp.async, 2 per thread) ----
    auto load_x = [&](int chunk, int slot) {
        const __half* b_base; int b_stride; int k0;
        if (chunk < NCHUNK_MAIN) {
            b_base = xh;  b_stride = IN_F; k0 = chunk * KBLK;
        } else {
            b_base = t2h; b_stride = RANK; k0 = 0;
        }
        uint32_t s_x = sb + OFF_XH + (uint32_t)slot * XH_STAGE_B;
#pragma unroll
        for (int i = 0; i < 2; ++i) {
            int idx = tid + i * THREADS;
            int row = idx >> 3, seg = idx & 7;
            cp16(s_x + (uint32_t)(row * PH + seg * 8) * 2,
                 b_base + (size_t)row * b_stride + k0 + seg * 8);
        }
    };

    // ---- prologue ----
    float4 rA[8], rB[8];
    ldg_w(0, rA);
    ldg_w(1, rB);
    load_x(0, 0); CP_COMMIT();
    load_x(1, 1); CP_COMMIT();
    load_x(2, 2); CP_COMMIT();

    float d[2][4][4];
#pragma unroll
    for (int mi = 0; mi < 2; ++mi)
#pragma unroll
        for (int ni = 0; ni < 4; ++ni)
#pragma unroll
            for (int r = 0; r < 4; ++r) d[mi][ni][r] = 0.f;

    // ---- mainloop: 65 iterations, 2 barriers each ----
    for (int it = 0; it < NCHUNK_TOT; ++it) {
        CP_WAITG2();       // X chunk `it` complete (own ops)
        __syncthreads();   // all threads' X chunk `it` visible; Wh reads of it-1 done

        // X refill: chunk it+3 into slot (it+3)&3 (slot of it-1, retired)
        {
            int nc = it + 3;
            if (nc < NCHUNK_TOT) load_x(nc, nc & 3);
            CP_COMMIT();
        }

        // W: publish chunk `it` from regs -> Wh; refill regs with chunk it+2
        if (it & 1) { sts_w(rB); if (it + 2 < NCHUNK_TOT) ldg_w(it + 2, rB); }
        else        { sts_w(rA); if (it + 2 < NCHUNK_TOT) ldg_w(it + 2, rA); }
        __syncthreads();   // Wh published

        const uint32_t wh_b = sb + OFF_WH;
        const uint32_t xb   = sb + OFF_XH + (uint32_t)(it & 3) * XH_STAGE_B;
#pragma unroll
        for (int kk = 0; kk < 4; ++kk) {
            const uint32_t k2 = kk * 32;   // 16 halfs = 32B
            uint32_t a0[4], a1[4], bq0[4], bq1[4];
            ldsm4(a0,  wh_b + a_rel0 + k2);
            ldsm4(a1,  wh_b + a_rel1 + k2);
            ldsm4(bq0, xb + b_rel0 + k2);
            ldsm4(bq1, xb + b_rel1 + k2);
            mma_f16(d[0][0], a0, bq0[0], bq0[1]);
            mma_f16(d[0][1], a0, bq0[2], bq0[3]);
            mma_f16(d[0][2], a0, bq1[0], bq1[1]);
            mma_f16(d[0][3], a0, bq1[2], bq1[3]);
            mma_f16(d[1][0], a1, bq0[0], bq0[1]);
            mma_f16(d[1][1], a1, bq0[2], bq0[3]);
            mma_f16(d[1][2], a1, bq1[0], bq1[1]);
            mma_f16(d[1][3], a1, bq1[2], bq1[3]);
        }
    }

    // ---- epilogue: D[m][n] -> out[n][m] ----
#pragma unroll
    for (int mi = 0; mi < 2; ++mi) {
#pragma unroll
        for (int ni = 0; ni < 4; ++ni) {
            int m = m_base + wm + mi * 16 + g;
            int n = wn + ni * 8 + 2 * t;
            out[(size_t)n * OUT_F + m]           = d[mi][ni][0];
            out[(size_t)(n + 1) * OUT_F + m]     = d[mi][ni][1];
            out[(size_t)n * OUT_F + m + 8]       = d[mi][ni][2];
            out[(size_t)(n + 1) * OUT_F + m + 8] = d[mi][ni][3];
        }
    }
}

// ---------------- host launch ----------------
extern "C" void kernel_launch(void* const* d_in, const int* in_sizes, int n_in,
                              void* d_out, int out_size) {
    const float* x  = (const float*)d_in[0];   // [64, 4096]
    const float* w  = (const float*)d_in[1];   // [16384, 4096]
    const float* lA = (const float*)d_in[2];   // [64, 4096]
    const float* lB = (const float*)d_in[3];   // [16384, 64]
    float* out = (float*)d_out;                // [64, 16384]

    void* xh_ptr = nullptr;
    void* t2_ptr = nullptr;
    void* part_ptr = nullptr;
    cudaGetSymbolAddress(&xh_ptr, g_xh);
    cudaGetSymbolAddress(&t2_ptr, g_t2h);
    cudaGetSymbolAddress(&part_ptr, g_part);

    prep_kernel<<<64, 256>>>(x, lA, (uint2*)xh_ptr, (float*)part_ptr);
    reduce_kernel<<<16, 256>>>((const float*)part_ptr, (__half*)t2_ptr);

    static int smem_set = 0;
    if (!smem_set) {
        cudaFuncSetAttribute(lora_main_kernel,
                             cudaFuncAttributeMaxDynamicSharedMemorySize, SMEM_BYTES);
        smem_set = 1;
    }
    lora_main_kernel<<<OUT_F / BLOCK_M, THREADS, SMEM_BYTES>>>(
        (const __half*)xh_ptr, w, lB, (const __half*)t2_ptr, out);
}

// round 13
// speedup vs baseline: 1.2670x; 1.2670x over previous
#include <cuda_runtime.h>
#include <cuda_fp16.h>
#include <cstdint>

// ---------------- problem constants ----------------
#define IN_F   4096
#define OUT_F  16384
#define NTOK   64
#define RANK   64

#define BLOCK_M 128          // out-features per CTA
#define KBLK    64           // K elems per pipeline stage
#define STAGES  4
#define THREADS 256
#define NCHUNK_MAIN (IN_F / KBLK)             // 64
#define NCHUNK_TOT  (NCHUNK_MAIN + 1)         // 65 (lora tail chunk)

// ---------------- main-kernel SMEM layout ----------------
#define P32        68                          // fp32 row pitch (floats)
#define W32_STAGE_F (BLOCK_M * P32)            // 8704 floats
#define W32_STAGE_B (W32_STAGE_F * 4)          // 34816 B
#define OFF_W32    0
#define PH         72                          // fp16 row pitch (halfs)
#define OFF_WH     (STAGES * W32_STAGE_B)      // 139264
#define WH_BYTES   (BLOCK_M * PH * 2)          // 18432
#define OFF_XH     (OFF_WH + WH_BYTES)         // 157696
#define XH_STAGE_B (NTOK * PH * 2)             // 9216
#define SMEM_BYTES (OFF_XH + STAGES * XH_STAGE_B)  // 194560

// device scratch
__device__ __align__(256) __half g_xh[NTOK * IN_F];    // x in fp16
__device__ __align__(256) __half g_t2h[NTOK * RANK];   // 2*(x@A^T) in fp16
__device__ __align__(256) float  g_part[64 * NTOK * RANK];  // K-slice partials

// ---------------- PTX helpers ----------------
__device__ __forceinline__ uint32_t smem_u32(const void* p) {
    uint32_t a;
    asm("{ .reg .u64 t; cvta.to.shared.u64 t, %1; cvt.u32.u64 %0, t; }" : "=r"(a) : "l"(p));
    return a;
}
__device__ __forceinline__ void cp16(uint32_t dst, const void* src) {
    asm volatile("cp.async.cg.shared.global [%0], [%1], 16;" :: "r"(dst), "l"(src));
}
#define CP_COMMIT() asm volatile("cp.async.commit_group;" ::: "memory")
#define CP_WAITG2() asm volatile("cp.async.wait_group 2;" ::: "memory")

__device__ __forceinline__ void ldsm4(uint32_t* r, uint32_t addr) {
    asm volatile("ldmatrix.sync.aligned.m8n8.x4.shared.b16 {%0,%1,%2,%3}, [%4];"
                 : "=r"(r[0]), "=r"(r[1]), "=r"(r[2]), "=r"(r[3]) : "r"(addr));
}
__device__ __forceinline__ void mma_f16(float* d, const uint32_t* a,
                                        uint32_t b0, uint32_t b1) {
    asm volatile(
        "mma.sync.aligned.m16n8k16.row.col.f32.f16.f16.f32 "
        "{%0,%1,%2,%3}, {%4,%5,%6,%7}, {%8,%9}, {%0,%1,%2,%3};"
        : "+f"(d[0]), "+f"(d[1]), "+f"(d[2]), "+f"(d[3])
        : "r"(a[0]), "r"(a[1]), "r"(a[2]), "r"(a[3]), "r"(b0), "r"(b1));
}
__device__ __forceinline__ uint32_t h2u(__half2 h) {
    return *reinterpret_cast<uint32_t*>(&h);
}
__device__ __forceinline__ float dot4(float4 a, float4 b) {
    return a.x * b.x + a.y * b.y + a.z * b.z + a.w * b.w;
}

// ---------------- prep: grid 64 (one wave). x2h slice + t2 K-slice partial ----------
// (benched 9.9us in R12)
__global__ void __launch_bounds__(256) prep_kernel(const float* __restrict__ x,
                                                   const float* __restrict__ A,
                                                   uint2* __restrict__ xh2,
                                                   float* __restrict__ part) {
    int tid = threadIdx.x;
    int s = blockIdx.x;                       // 0..63
    // ---- x -> fp16: 65536 float4 over 64 blocks = 4/thread ----
    {
        const float4* x4 = (const float4*)x;
        int base = s * 1024;
#pragma unroll
        for (int i = 0; i < 4; ++i) {
            int idx = base + tid + i * 256;
            float4 v = x4[idx];
            uint2 o;
            o.x = h2u(__floats2half2_rn(v.x, v.y));
            o.y = h2u(__floats2half2_rn(v.z, v.w));
            xh2[idx] = o;
        }
    }
    // ---- t2 partial for K-slice s ----
    __shared__ float4 xs[64][17];
    __shared__ float4 as[64][17];
#pragma unroll
    for (int i = 0; i < 4; ++i) {
        int idx = tid + i * 256;
        int row = idx >> 4, c = idx & 15;
        xs[row][c] = ((const float4*)x)[(size_t)row * (IN_F / 4) + s * 16 + c];
        as[row][c] = ((const float4*)A)[(size_t)row * (IN_F / 4) + s * 16 + c];
    }
    __syncthreads();
    int ti = tid >> 4, tj = tid & 15;
    float acc[4][4];
#pragma unroll
    for (int r = 0; r < 4; ++r)
#pragma unroll
        for (int c = 0; c < 4; ++c) acc[r][c] = 0.f;
#pragma unroll
    for (int kc = 0; kc < 16; ++kc) {
        float4 xv[4], av[4];
#pragma unroll
        for (int r = 0; r < 4; ++r) xv[r] = xs[ti * 4 + r][kc];
#pragma unroll
        for (int c = 0; c < 4; ++c) av[c] = as[tj * 4 + c][kc];
#pragma unroll
        for (int r = 0; r < 4; ++r)
#pragma unroll
            for (int c = 0; c < 4; ++c) acc[r][c] += dot4(xv[r], av[c]);
    }
    float* dst = part + (size_t)s * (NTOK * RANK);
#pragma unroll
    for (int r = 0; r < 4; ++r)
#pragma unroll
        for (int c = 0; c < 4; ++c)
            dst[(ti * 4 + r) * RANK + tj * 4 + c] = acc[r][c];
}

// ---------------- reduce: 64 partials -> t2h = fp16(2*sum); 8-way MLP ------------
__global__ void __launch_bounds__(256) reduce_kernel(const float* __restrict__ part,
                                                     __half* __restrict__ t2) {
    int idx = blockIdx.x * 256 + threadIdx.x;     // 0..4095
    float s[8];
#pragma unroll
    for (int j = 0; j < 8; ++j) s[j] = 0.f;
#pragma unroll
    for (int b = 0; b < 64; b += 8)
#pragma unroll
        for (int j = 0; j < 8; ++j)
            s[j] += part[(size_t)(b + j) * 4096 + idx];
    float r = ((s[0] + s[1]) + (s[2] + s[3])) + ((s[4] + s[5]) + (s[6] + s[7]));
    t2[idx] = __float2half_rn(2.0f * r);
}

// ---------------- main fused GEMM (EXACT R10-proposal kernel; benched main ~74us) ---
// 128 CTAs, 256 threads (8 warps: 4M x 2N), KBLK=64, 4-stage cp.async (wait depth 2).
__global__ void __launch_bounds__(THREADS, 1) lora_main_kernel(
    const __half* __restrict__ xh,     // [64,4096] fp16
    const float*  __restrict__ w,      // [16384,4096] fp32
    const float*  __restrict__ lB,     // [16384,64] fp32
    const __half* __restrict__ t2h,    // [64,64] fp16 (incl. 2x scale)
    float* __restrict__ out)           // [64,16384]
{
    extern __shared__ __align__(16) char smem_c[];
    float* smem_f = (float*)smem_c;
    const uint32_t sb = smem_u32(smem_c);
    const int tid  = threadIdx.x;
    const int wid  = tid >> 5;
    const int lane = tid & 31;
    const int g = lane >> 2;
    const int t = lane & 3;
    const int wm = (wid & 3) * 32;    // warp M offset
    const int wn = (wid >> 2) * 32;   // warp N offset (tokens)
    const int m_base = blockIdx.x * BLOCK_M;

    // ---- per-lane ldmatrix offsets ----
    const int a_row  = (lane & 7) + ((lane >> 3) & 1) * 8;
    const uint32_t a_byte = ((lane >> 4) & 1) * 16;
    const uint32_t a_rel0 = (uint32_t)(wm + a_row) * (PH * 2) + a_byte;
    const uint32_t a_rel1 = a_rel0 + 16 * (PH * 2);
    const int b_row  = (lane & 7) + ((lane >> 4) & 1) * 8;
    const uint32_t b_byte = ((lane >> 3) & 1) * 16;
    const uint32_t b_rel0 = (uint32_t)(wn + b_row) * (PH * 2) + b_byte;
    const uint32_t b_rel1 = b_rel0 + 16 * (PH * 2);

    // ---- stage loader: W 128x64 fp32 (8 cp/thread) + X 64x64 fp16 (2 cp/thread) ----
    auto load_stage = [&](int chunk, int stage) {
        const float* a_base; int a_stride;
        const __half* b_base; int b_stride;
        int k0;
        if (chunk < NCHUNK_MAIN) {
            a_base = w + (size_t)m_base * IN_F;  a_stride = IN_F;
            b_base = xh;                         b_stride = IN_F;
            k0 = chunk * KBLK;
        } else {
            a_base = lB + (size_t)m_base * RANK; a_stride = RANK;
            b_base = t2h;                        b_stride = RANK;
            k0 = 0;
        }
        uint32_t s_w = sb + OFF_W32 + (uint32_t)stage * W32_STAGE_B;
#pragma unroll
        for (int i = 0; i < 8; ++i) {
            int idx = tid + i * THREADS;
            int row = idx >> 4, c = idx & 15;
            cp16(s_w + (uint32_t)(row * P32 + c * 4) * 4,
                 a_base + (size_t)row * a_stride + k0 + c * 4);
        }
        uint32_t s_x = sb + OFF_XH + (uint32_t)stage * XH_STAGE_B;
#pragma unroll
        for (int i = 0; i < 2; ++i) {
            int idx = tid + i * THREADS;
            int row = idx >> 3, seg = idx & 7;
            cp16(s_x + (uint32_t)(row * PH + seg * 8) * 2,
                 b_base + (size_t)row * b_stride + k0 + seg * 8);
        }
    };

    // ---- convert: thread covers (row = tid&127, half = tid>>7) -> 32 floats ----
    const int cvt_row  = tid & 127;
    const int cvt_half = tid >> 7;
    auto convert = [&](int slot) {
        const float* srcp = smem_f + slot * W32_STAGE_F + cvt_row * P32 + cvt_half * 32;
        __half* whp = (__half*)(smem_c + OFF_WH) + cvt_row * PH + cvt_half * 32;
#pragma unroll
        for (int q = 0; q < 2; ++q) {
            float4 v0 = ((const float4*)(srcp + q * 16))[0];
            float4 v1 = ((const float4*)(srcp + q * 16))[1];
            float4 v2 = ((const float4*)(srcp + q * 16))[2];
            float4 v3 = ((const float4*)(srcp + q * 16))[3];
            uint4 p0, p1;
            p0.x = h2u(__floats2half2_rn(v0.x, v0.y));
            p0.y = h2u(__floats2half2_rn(v0.z, v0.w));
            p0.z = h2u(__floats2half2_rn(v1.x, v1.y));
            p0.w = h2u(__floats2half2_rn(v1.z, v1.w));
            p1.x = h2u(__floats2half2_rn(v2.x, v2.y));
            p1.y = h2u(__floats2half2_rn(v2.z, v2.w));
            p1.z = h2u(__floats2half2_rn(v3.x, v3.y));
            p1.w = h2u(__floats2half2_rn(v3.z, v3.w));
            ((uint4*)(whp + q * 16))[0] = p0;
            ((uint4*)(whp + q * 16 + 8))[0] = p1;
        }
    };

    // ---- prologue: chunks 0,1,2 in flight ----
    load_stage(0, 0); CP_COMMIT();
    load_stage(1, 1); CP_COMMIT();
    load_stage(2, 2); CP_COMMIT();

    float d[2][4][4];
#pragma unroll
    for (int mi = 0; mi < 2; ++mi)
#pragma unroll
        for (int ni = 0; ni < 4; ++ni)
#pragma unroll
            for (int r = 0; r < 4; ++r) d[mi][ni][r] = 0.f;

    // ---- mainloop: 65 iterations ----
    int s = 0;        // slot of chunk `it`
    for (int it = 0; it < NCHUNK_TOT; ++it) {
        CP_WAITG2();       // chunk `it` complete (own ops); it+1,it+2 may pend
        __syncthreads();   // chunk `it` visible to ALL; prior reads of slots done

        // refill chunk it+3 into slot (it+3)&3 FIRST (requests out before convert)
        {
            int nc = it + 3;
            if (nc < NCHUNK_TOT) load_stage(nc, nc & 3);
            CP_COMMIT();
        }

        convert(s);        // W32[s] -> Wh (fp16)
        __syncthreads();   // Wh published

        const uint32_t wh_b = sb + OFF_WH;
        const uint32_t xb   = sb + OFF_XH + (uint32_t)s * XH_STAGE_B;
#pragma unroll
        for (int kk = 0; kk < 4; ++kk) {
            const uint32_t k2 = kk * 32;   // 16 halfs = 32B
            uint32_t a0[4], a1[4], bq0[4], bq1[4];
            ldsm4(a0,  wh_b + a_rel0 + k2);
            ldsm4(a1,  wh_b + a_rel1 + k2);
            ldsm4(bq0, xb + b_rel0 + k2);
            ldsm4(bq1, xb + b_rel1 + k2);
            mma_f16(d[0][0], a0, bq0[0], bq0[1]);
            mma_f16(d[0][1], a0, bq0[2], bq0[3]);
            mma_f16(d[0][2], a0, bq1[0], bq1[1]);
            mma_f16(d[0][3], a0, bq1[2], bq1[3]);
            mma_f16(d[1][0], a1, bq0[0], bq0[1]);
            mma_f16(d[1][1], a1, bq0[2], bq0[3]);
            mma_f16(d[1][2], a1, bq1[0], bq1[1]);
            mma_f16(d[1][3], a1, bq1[2], bq1[3]);
        }

        s = (s + 1) & 3;
    }

    // ---- epilogue: D[m][n] -> out[n][m] ----
#pragma unroll
    for (int mi = 0; mi < 2; ++mi) {
#pragma unroll
        for (int ni = 0; ni < 4; ++ni) {
            int m = m_base + wm + mi * 16 + g;
            int n = wn + ni * 8 + 2 * t;
            out[(size_t)n * OUT_F + m]           = d[mi][ni][0];
            out[(size_t)(n + 1) * OUT_F + m]     = d[mi][ni][1];
            out[(size_t)n * OUT_F + m + 8]       = d[mi][ni][2];
            out[(size_t)(n + 1) * OUT_F + m + 8] = d[mi][ni][3];
        }
    }
}

// ---------------- host launch ----------------
extern "C" void kernel_launch(void* const* d_in, const int* in_sizes, int n_in,
                              void* d_out, int out_size) {
    const float* x  = (const float*)d_in[0];   // [64, 4096]
    const float* w  = (const float*)d_in[1];   // [16384, 4096]
    const float* lA = (const float*)d_in[2];   // [64, 4096]
    const float* lB = (const float*)d_in[3];   // [16384, 64]
    float* out = (float*)d_out;                // [64, 16384]

    void* xh_ptr = nullptr;
    void* t2_ptr = nullptr;
    void* part_ptr = nullptr;
    cudaGetSymbolAddress(&xh_ptr, g_xh);
    cudaGetSymbolAddress(&t2_ptr, g_t2h);
    cudaGetSymbolAddress(&part_ptr, g_part);

    prep_kernel<<<64, 256>>>(x, lA, (uint2*)xh_ptr, (float*)part_ptr);
    reduce_kernel<<<16, 256>>>((const float*)part_ptr, (__half*)t2_ptr);

    static int smem_set = 0;
    if (!smem_set) {
        cudaFuncSetAttribute(lora_main_kernel,
                             cudaFuncAttributeMaxDynamicSharedMemorySize, SMEM_BYTES);
        smem_set = 1;
    }
    lora_main_kernel<<<OUT_F / BLOCK_M, THREADS, SMEM_BYTES>>>(
        (const __half*)xh_ptr, w, lB, (const __half*)t2_ptr, out);
}